// round 1
// baseline (speedup 1.0000x reference)
#include <cuda_runtime.h>
#include <cuda_bf16.h>

// CRF forward scan.
// score'[i] = log( sum_j exp(trans[i][j]) * exp(score[j] - M) ) + M + y[t][i]
// E = exp(trans) precomputed once, held in registers (64 floats/thread).
// One CTA per batch element; 256 threads: thread (i = tid&127, h = tid>>7)
// accumulates the j-half [h*64, h*64+64) of output state i.

#define KDIM 128
#define NEGV -10000.0f

__global__ __launch_bounds__(256, 1)
void crf_fwd_kernel(const float* __restrict__ y,
                    const float* __restrict__ mask,
                    const float* __restrict__ trans,
                    float* __restrict__ out,
                    int T) {
    const int b    = blockIdx.x;
    const int tid  = threadIdx.x;
    const int i    = tid & (KDIM - 1);
    const int h    = tid >> 7;          // 0 or 1: which j-half
    const int lane = tid & 31;
    const int warp = tid >> 5;

    __shared__ float p_sh[KDIM];        // exp(score - M)
    __shared__ float part_sh[KDIM];     // h==1 partial sums
    __shared__ float redm[4];           // cross-warp max (warps 0-3)
    __shared__ float reds[4];           // final sum reduce

    // ---- One-time: E[jj] = exp(trans[i][h*64 + jj]) into registers ----
    float E[64];
    const float4* t4 = reinterpret_cast<const float4*>(trans + i * KDIM + h * 64);
    #pragma unroll
    for (int q = 0; q < 16; q++) {
        float4 v = t4[q];
        E[4*q+0] = expf(v.x);
        E[4*q+1] = expf(v.y);
        E[4*q+2] = expf(v.z);
        E[4*q+3] = expf(v.w);
    }

    // ---- Init score (only h==0 threads own the live score) ----
    float score = (i == 2) ? 0.0f : NEGV;   // SOS_IDX = 2

    const float* yb = y    + (size_t)b * T * KDIM;
    const float* mb = mask + (size_t)b * T;

    float yv = 0.0f, mv = 0.0f;
    if (h == 0) { yv = yb[i]; mv = mb[0]; }

    float M = 0.0f;

    for (int t = 0; t < T; t++) {
        // ---- 1. M = max_j score_j (h==0 warps only) ----
        if (h == 0) {
            float m = score;
            m = fmaxf(m, __shfl_xor_sync(0xffffffffu, m, 16));
            m = fmaxf(m, __shfl_xor_sync(0xffffffffu, m, 8));
            m = fmaxf(m, __shfl_xor_sync(0xffffffffu, m, 4));
            m = fmaxf(m, __shfl_xor_sync(0xffffffffu, m, 2));
            m = fmaxf(m, __shfl_xor_sync(0xffffffffu, m, 1));
            if (lane == 0) redm[warp] = m;
        }
        __syncthreads();                               // S1
        if (h == 0) {
            M = fmaxf(fmaxf(redm[0], redm[1]), fmaxf(redm[2], redm[3]));
            p_sh[i] = __expf(score - M);
        }
        __syncthreads();                               // S2

        // ---- prefetch next step's y / mask (overlaps matvec) ----
        float yn = 0.0f, mn = 0.0f;
        if (h == 0 && t + 1 < T) {
            yn = yb[(size_t)(t + 1) * KDIM + i];
            mn = mb[t + 1];
        }

        // ---- 2. matvec: acc = sum_jj E[jj] * p[h*64 + jj] ----
        const float4* p4 = reinterpret_cast<const float4*>(p_sh + h * 64);
        float a0 = 0.0f, a1 = 0.0f, a2 = 0.0f, a3 = 0.0f;
        #pragma unroll
        for (int q = 0; q < 16; q++) {
            float4 pv = p4[q];
            a0 = fmaf(E[4*q+0], pv.x, a0);
            a1 = fmaf(E[4*q+1], pv.y, a1);
            a2 = fmaf(E[4*q+2], pv.z, a2);
            a3 = fmaf(E[4*q+3], pv.w, a3);
        }
        float acc = (a0 + a1) + (a2 + a3);
        if (h == 1) part_sh[i] = acc;
        __syncthreads();                               // S3

        // ---- 3. combine halves, log, add M + y, masked update ----
        if (h == 0) {
            float total = acc + part_sh[i];
            float s = __logf(total) + M + yv;          // log(0) -> -inf: OK
            score = (mv != 0.0f) ? s : score;          // select avoids -inf*0 NaN
            yv = yn; mv = mn;
        }
    }

    // ---- Final: out[b] = logsumexp_i(score_i) ----
    if (h == 0) {
        float m = score;
        m = fmaxf(m, __shfl_xor_sync(0xffffffffu, m, 16));
        m = fmaxf(m, __shfl_xor_sync(0xffffffffu, m, 8));
        m = fmaxf(m, __shfl_xor_sync(0xffffffffu, m, 4));
        m = fmaxf(m, __shfl_xor_sync(0xffffffffu, m, 2));
        m = fmaxf(m, __shfl_xor_sync(0xffffffffu, m, 1));
        if (lane == 0) redm[warp] = m;
    }
    __syncthreads();
    float Mf = fmaxf(fmaxf(redm[0], redm[1]), fmaxf(redm[2], redm[3]));
    if (h == 0) {
        float e = __expf(score - Mf);
        e += __shfl_xor_sync(0xffffffffu, e, 16);
        e += __shfl_xor_sync(0xffffffffu, e, 8);
        e += __shfl_xor_sync(0xffffffffu, e, 4);
        e += __shfl_xor_sync(0xffffffffu, e, 2);
        e += __shfl_xor_sync(0xffffffffu, e, 1);
        if (lane == 0) reds[warp] = e;
    }
    __syncthreads();
    if (tid == 0) {
        out[b] = __logf((reds[0] + reds[1]) + (reds[2] + reds[3])) + Mf;
    }
}

extern "C" void kernel_launch(void* const* d_in, const int* in_sizes, int n_in,
                              void* d_out, int out_size) {
    const float* y     = (const float*)d_in[0];   // (B, T, K) f32
    const float* mask  = (const float*)d_in[1];   // (B, T)    f32
    const float* trans = (const float*)d_in[2];   // (K, K)    f32
    float* out = (float*)d_out;                   // (B,)      f32

    const int B = out_size;                       // 64
    const int T = in_sizes[1] / B;                // 256

    crf_fwd_kernel<<<B, 256>>>(y, mask, trans, out, T);
}

// round 2
// speedup vs baseline: 2.0924x; 2.0924x over previous
#include <cuda_runtime.h>

// CRF forward scan, probability domain (scaled HMM forward).
//   state: s_t[i] with  score_t[i] = log(s_t[i]) + eacc*ln2
//   step:  q_i = sum_j E[i][j] * s_t[j];  s_{t+1}[i] = q_i * exp(y[t][i]) * (1/Z_t)
//          Z_t = 2^(exponent of max_i s_t[i])  -> exact power-of-two rescale
//   E = exp(trans) lives in registers as packed f32x2 pairs.
//   128 threads, 1 CTA per batch, double-buffered p in SMEM, ONE sync per step.
//   Masked steps (prefix mask) are skipped entirely via len = sum(mask).

#define KDIM 128

__device__ __forceinline__ unsigned long long pack2(float lo, float hi) {
    unsigned long long r;
    asm("mov.b64 %0, {%1, %2};" : "=l"(r) : "f"(lo), "f"(hi));
    return r;
}
__device__ __forceinline__ void fma2(unsigned long long& a,
                                     unsigned long long x,
                                     unsigned long long p) {
    asm("fma.rn.f32x2 %0, %1, %2, %0;" : "+l"(a) : "l"(x), "l"(p));
}
__device__ __forceinline__ unsigned long long add2(unsigned long long a,
                                                   unsigned long long b) {
    unsigned long long r;
    asm("add.rn.f32x2 %0, %1, %2;" : "=l"(r) : "l"(a), "l"(b));
    return r;
}

__global__ __launch_bounds__(128, 1)
void crf_fwd_kernel(const float* __restrict__ y,
                    const float* __restrict__ mask,
                    const float* __restrict__ trans,
                    float* __restrict__ out,
                    int T) {
    const int b    = blockIdx.x;
    const int i    = threadIdx.x;      // 0..127 : output state
    const int lane = i & 31;
    const int warp = i >> 5;

    __shared__ float    pbuf[2][KDIM];
    __shared__ unsigned wmax[2][4];    // per-warp max bits, double-buffered
    __shared__ float    redf[4];
    __shared__ int      len_sh;

    // ---- one-time: E row into registers, packed as 64 f32x2 pairs ----
    unsigned long long E2[64];
    {
        const float4* t4 = reinterpret_cast<const float4*>(trans + (size_t)i * KDIM);
        #pragma unroll
        for (int q = 0; q < 32; q++) {
            float4 v = t4[q];
            E2[2*q]   = pack2(expf(v.x), expf(v.y));
            E2[2*q+1] = pack2(expf(v.z), expf(v.w));
        }
    }

    // ---- init state, renorm buffer, length ----
    if (i == 0) len_sh = 0;
    pbuf[0][i] = (i == 2) ? 1.0f : 0.0f;          // SOS_IDX = 2
    if (i < 4) { wmax[0][i] = 0x3f800000u; }      // Z_0 = 1.0
    __syncthreads();
    {
        const float* mb = mask + (size_t)b * T;
        int cnt = 0;
        for (int t = i; t < T; t += KDIM) cnt += (mb[t] != 0.0f);
        cnt = __reduce_add_sync(0xffffffffu, cnt);
        if (lane == 0) atomicAdd(&len_sh, cnt);
    }
    __syncthreads();
    const int len = len_sh;

    // ---- y prefetch pipeline (3 deep) ----
    const float* yb = y + (size_t)b * T * KDIM + i;
    float ey = 0.0f, y1 = 0.0f, y2 = 0.0f;
    if (len > 0) ey = __expf(yb[0]);
    if (1 < T)   y1 = yb[(size_t)KDIM];
    if (2 < T)   y2 = yb[(size_t)2 * KDIM];

    int cur  = 0;
    int eacc = 0;
    float s  = pbuf[0][i];

    for (int t = 0; t < len; t++) {
        // Z_t from previous iteration's per-warp maxima (exact power of two)
        unsigned mb0 = max(max(wmax[cur][0], wmax[cur][1]),
                           max(wmax[cur][2], wmax[cur][3]));
        int Ee   = (int)(mb0 >> 23);
        float rz = __uint_as_float((unsigned)(254 - Ee) << 23);  // 1 / 2^(Ee-127)
        eacc    += Ee - 127;

        // matvec: q = sum_j E[i][j] * s_t[j]   (broadcast LDS, packed FFMA)
        const float4* p4 = reinterpret_cast<const float4*>(pbuf[cur]);
        unsigned long long a0=0,a1=0,a2=0,a3=0,a4=0,a5=0,a6=0,a7=0;
        #pragma unroll
        for (int q = 0; q < 8; q++) {
            float4 v0 = p4[4*q+0];
            float4 v1 = p4[4*q+1];
            float4 v2 = p4[4*q+2];
            float4 v3 = p4[4*q+3];
            fma2(a0, E2[8*q+0], pack2(v0.x, v0.y));
            fma2(a1, E2[8*q+1], pack2(v0.z, v0.w));
            fma2(a2, E2[8*q+2], pack2(v1.x, v1.y));
            fma2(a3, E2[8*q+3], pack2(v1.z, v1.w));
            fma2(a4, E2[8*q+4], pack2(v2.x, v2.y));
            fma2(a5, E2[8*q+5], pack2(v2.z, v2.w));
            fma2(a6, E2[8*q+6], pack2(v3.x, v3.y));
            fma2(a7, E2[8*q+7], pack2(v3.z, v3.w));
        }
        unsigned long long aa = add2(add2(add2(a0,a1), add2(a2,a3)),
                                     add2(add2(a4,a5), add2(a6,a7)));
        float qlo = __uint_as_float((unsigned)(aa & 0xffffffffu));
        float qhi = __uint_as_float((unsigned)(aa >> 32));
        s = (qlo + qhi) * ey * rz;                 // s >= 0 always

        // per-warp max of new s (positive float bits are order-preserving)
        unsigned wm = __reduce_max_sync(0xffffffffu, __float_as_uint(s));
        if (lane == 0) wmax[cur ^ 1][warp] = wm;
        pbuf[cur ^ 1][i] = s;

        // rotate y pipeline (off critical path)
        ey = __expf(y1);
        y1 = y2;
        int tf = t + 3;
        y2 = (tf < T) ? yb[(size_t)tf * KDIM] : 0.0f;

        __syncthreads();
        cur ^= 1;
    }

    // ---- final: out[b] = log(sum_i s[i]) + eacc*ln2 ----
    float v = pbuf[cur][i];
    float e = v;
    e += __shfl_xor_sync(0xffffffffu, e, 16);
    e += __shfl_xor_sync(0xffffffffu, e, 8);
    e += __shfl_xor_sync(0xffffffffu, e, 4);
    e += __shfl_xor_sync(0xffffffffu, e, 2);
    e += __shfl_xor_sync(0xffffffffu, e, 1);
    if (lane == 0) redf[warp] = e;
    __syncthreads();
    if (i == 0) {
        float tot = (redf[0] + redf[1]) + (redf[2] + redf[3]);
        out[b] = logf(tot) + (float)((double)eacc * 0.6931471805599453);
    }
}

extern "C" void kernel_launch(void* const* d_in, const int* in_sizes, int n_in,
                              void* d_out, int out_size) {
    const float* y     = (const float*)d_in[0];   // (B, T, K) f32
    const float* mask  = (const float*)d_in[1];   // (B, T)    f32
    const float* trans = (const float*)d_in[2];   // (K, K)    f32
    float* out = (float*)d_out;                   // (B,)      f32

    const int B = out_size;                       // 64
    const int T = in_sizes[1] / B;                // 256

    crf_fwd_kernel<<<B, 128>>>(y, mask, trans, out, T);
}